// round 8
// baseline (speedup 1.0000x reference)
#include <cuda_runtime.h>
#include <cuda_bf16.h>
#include <cstdint>

#define B_   16
#define C_   128
#define HW_  1024
#define NH_  4
#define COND_ 32

// Scratch (device globals; no allocations allowed)
__device__ __nv_bfloat16  g_h16 [B_*C_*HW_];        // groupnorm output [b][c][s]
__device__ __nv_bfloat16  g_q16 [B_*NH_*HW_*C_];    // q [b*4+e][s][c]
__device__ __nv_bfloat16  g_k16 [B_*NH_*HW_*C_];
__device__ __nv_bfloat16  g_v16 [B_*NH_*HW_*C_];
__device__ __nv_bfloat16  g_hh16[B_*6*C_*HW_];      // [16][768][1024]
// bf16 weight/cond copies (converted once per call)
__device__ __nv_bfloat16  g_w0b[160*512];
__device__ __nv_bfloat16  g_w1b[160*512];
__device__ __nv_bfloat16  g_w2b[160*512];
__device__ __nv_bfloat16  g_w3b[768*128];
__device__ __nv_bfloat16  g_qcb[(B_/2)*COND_*HW_];
__device__ __nv_bfloat16  g_kab[(B_/2)*COND_*HW_];
__device__ __nv_bfloat16  g_kbb[(B_/2)*COND_*HW_];

// ---------------------------------------------------------------------------
__device__ __forceinline__ uint32_t smem_u32(const void* p) {
    uint32_t a;
    asm("{ .reg .u64 t; cvta.to.shared.u64 t, %1; cvt.u32.u64 %0, t; }"
        : "=r"(a) : "l"(p));
    return a;
}
__device__ __forceinline__ uint32_t pack_bf16(float lo, float hi) {
    uint32_t r;
    asm("cvt.rn.bf16x2.f32 %0, %1, %2;" : "=r"(r) : "f"(hi), "f"(lo));
    return r;
}
__device__ __forceinline__ float fast_ex2(float x) {
    float y;
    asm("ex2.approx.f32 %0, %1;" : "=f"(y) : "f"(x));
    return y;
}
__device__ __forceinline__ void mma_bf16(float c[4], const uint32_t a[4],
                                         uint32_t b0, uint32_t b1) {
    asm volatile("mma.sync.aligned.m16n8k16.row.col.f32.bf16.bf16.f32 "
        "{%0,%1,%2,%3}, {%4,%5,%6,%7}, {%8,%9}, {%0,%1,%2,%3};"
        : "+f"(c[0]), "+f"(c[1]), "+f"(c[2]), "+f"(c[3])
        : "r"(a[0]), "r"(a[1]), "r"(a[2]), "r"(a[3]), "r"(b0), "r"(b1));
}
__device__ __forceinline__ void ldsm_x4(uint32_t r[4], uint32_t addr) {
    asm volatile("ldmatrix.sync.aligned.m8n8.x4.shared.b16 {%0,%1,%2,%3}, [%4];"
        : "=r"(r[0]), "=r"(r[1]), "=r"(r[2]), "=r"(r[3]) : "r"(addr));
}
__device__ __forceinline__ void ldsm_x4t(uint32_t r[4], uint32_t addr) {
    asm volatile("ldmatrix.sync.aligned.m8n8.x4.trans.shared.b16 {%0,%1,%2,%3}, [%4];"
        : "=r"(r[0]), "=r"(r[1]), "=r"(r[2]), "=r"(r[3]) : "r"(addr));
}
__device__ __forceinline__ void cp_async16(uint32_t dst, const void* src) {
    asm volatile("cp.async.cg.shared.global [%0], [%1], 16;"
                 :: "r"(dst), "l"(src) : "memory");
}
#define CP_COMMIT() asm volatile("cp.async.commit_group;" ::: "memory")
#define CP_WAIT1()  asm volatile("cp.async.wait_group 1;" ::: "memory")
#define CP_WAIT0()  asm volatile("cp.async.wait_group 0;" ::: "memory")

// ---------------------------------------------------------------------------
// fp32 -> bf16 conversion of weights + cond tensors (once per call)
// ---------------------------------------------------------------------------
__global__ void __launch_bounds__(256) cvt_kernel(
    const float* __restrict__ W0, const float* __restrict__ W1,
    const float* __restrict__ W2, const float* __restrict__ W3,
    const float* __restrict__ qc, const float* __restrict__ ka,
    const float* __restrict__ kb)
{
    const float* src; __nv_bfloat16* dst; int n;
    switch (blockIdx.y) {
        case 0: src = W0; dst = g_w0b; n = 160*512;          break;
        case 1: src = W1; dst = g_w1b; n = 160*512;          break;
        case 2: src = W2; dst = g_w2b; n = 160*512;          break;
        case 3: src = W3; dst = g_w3b; n = 768*128;          break;
        case 4: src = qc; dst = g_qcb; n = (B_/2)*COND_*HW_; break;
        case 5: src = ka; dst = g_kab; n = (B_/2)*COND_*HW_; break;
        default: src = kb; dst = g_kbb; n = (B_/2)*COND_*HW_; break;
    }
    for (int i = (blockIdx.x*256 + threadIdx.x)*4; i < n; i += 256*256*4) {
        float4 v = *(const float4*)&src[i];
        *(uint2*)&dst[i] = make_uint2(pack_bf16(v.x, v.y), pack_bf16(v.z, v.w));
    }
}

// ---------------------------------------------------------------------------
// GroupNorm -> bf16
// ---------------------------------------------------------------------------
__global__ void __launch_bounds__(256) gn_kernel(
    const float* __restrict__ x, const float* __restrict__ scale,
    const float* __restrict__ bias, __nv_bfloat16* __restrict__ h)
{
    int b = blockIdx.x >> 5, grp = blockIdx.x & 31;
    const float* xp = x + (size_t)(b*C_ + grp*4)*HW_;
    __nv_bfloat16* hp = h + (size_t)(b*C_ + grp*4)*HW_;

    float s = 0.f, ss = 0.f;
    for (int i = threadIdx.x; i < 2048; i += 256) {
        float2 v = *(const float2*)&xp[i*2];
        s += v.x + v.y; ss += v.x*v.x + v.y*v.y;
    }
    #pragma unroll
    for (int o = 16; o; o >>= 1) {
        s  += __shfl_xor_sync(~0u, s,  o);
        ss += __shfl_xor_sync(~0u, ss, o);
    }
    __shared__ float sh_s[8], sh_ss[8];
    int w = threadIdx.x >> 5;
    if ((threadIdx.x & 31) == 0) { sh_s[w] = s; sh_ss[w] = ss; }
    __syncthreads();
    if (threadIdx.x < 32) {
        s  = (threadIdx.x < 8) ? sh_s [threadIdx.x] : 0.f;
        ss = (threadIdx.x < 8) ? sh_ss[threadIdx.x] : 0.f;
        #pragma unroll
        for (int o = 4; o; o >>= 1) {
            s  += __shfl_xor_sync(~0u, s,  o);
            ss += __shfl_xor_sync(~0u, ss, o);
        }
        if (threadIdx.x == 0) { sh_s[0] = s; sh_ss[0] = ss; }
    }
    __syncthreads();
    float mean = sh_s[0] * (1.f/4096.f);
    float var  = sh_ss[0] * (1.f/4096.f) - mean*mean;
    float inv  = rsqrtf(var + 1e-6f);
    for (int i = threadIdx.x*2; i < 4096; i += 512) {
        int c = grp*4 + (i >> 10);
        float sc = scale[c], bi = bias[c];
        float2 v = *(const float2*)&xp[i];
        *(uint32_t*)&hp[i] = pack_bf16((v.x - mean)*inv*sc + bi,
                                       (v.y - mean)*inv*sc + bi);
    }
}

// ---------------------------------------------------------------------------
// QKV projection: bf16 mma + ldmatrix + cp.async double-buffered staging.
// ---------------------------------------------------------------------------
__global__ void __launch_bounds__(256, 2) proj_bf16_kernel(
    const __nv_bfloat16* __restrict__ h,
    const float* __restrict__ b0, const float* __restrict__ b1,
    const float* __restrict__ b2,
    __nv_bfloat16* __restrict__ q16, __nv_bfloat16* __restrict__ k16,
    __nv_bfloat16* __restrict__ v16)
{
    int pt = blockIdx.x;
    int e  = blockIdx.y;
    int b  = blockIdx.z / 3, pr = blockIdx.z % 3;

    const __nv_bfloat16* Wb; const float* bias; const __nv_bfloat16* cond;
    __nv_bfloat16* dstb;
    if (pr == 0) { Wb = g_w0b; bias = b0; dstb = q16; cond = g_qcb + (size_t)(b>>1)*COND_*HW_; }
    else {
        cond = (((b & 1) ? g_kbb : g_kab)) + (size_t)(b>>1)*COND_*HW_;
        if (pr == 1) { Wb = g_w1b; bias = b1; dstb = k16; }
        else         { Wb = g_w2b; bias = b2; dstb = v16; }
    }
    const __nv_bfloat16* hb = h + (size_t)b*C_*HW_;
    __nv_bfloat16* dst = dstb + (size_t)(b*NH_ + e)*HW_*C_;

    __shared__ __nv_bfloat16 Xs[2][32*136];
    __shared__ __nv_bfloat16 Ws[2][32*136];
    const uint32_t xs_base0 = smem_u32(&Xs[0][0]);
    const uint32_t xs_base1 = smem_u32(&Xs[1][0]);
    const uint32_t ws_base0 = smem_u32(&Ws[0][0]);
    const uint32_t ws_base1 = smem_u32(&Ws[1][0]);

    const int tid  = threadIdx.x;
    const int warp = tid >> 5;
    const int lane = tid & 31;
    const int g    = lane >> 2;
    const int t    = lane & 3;
    const int q0   = warp * 16;

    const int arow = (lane & 7) + ((lane >> 4) & 1)*8;
    const int acol = q0 + ((lane >> 3) & 1)*8;
    const int brow = (lane & 7) + ((lane >> 3) & 1)*8;
    const int bcol = (lane >> 4)*8;

    auto stage = [&](int ch, int st) {
        uint32_t xd = st ? xs_base1 : xs_base0;
        uint32_t wd = st ? ws_base1 : ws_base0;
        const __nv_bfloat16* xsrc = (ch < 4) ? (hb + (size_t)(ch*32)*HW_ + pt*128)
                                             : (cond + pt*128);
        const __nv_bfloat16* wsrc = Wb + (size_t)(ch*32)*512 + e*128;
        #pragma unroll
        for (int it = 0; it < 2; it++) {
            int idx = it*256 + tid;
            int r = idx >> 4, c8 = idx & 15;
            cp_async16(xd + (uint32_t)(r*136 + c8*8)*2, xsrc + (size_t)r*HW_ + c8*8);
            cp_async16(wd + (uint32_t)(r*136 + c8*8)*2, wsrc + (size_t)r*512 + c8*8);
        }
    };

    float o[16][4];
    #pragma unroll
    for (int ct = 0; ct < 16; ct++)
        #pragma unroll
        for (int j = 0; j < 4; j++) o[ct][j] = 0.f;

    stage(0, 0); CP_COMMIT();

    for (int ch = 0; ch < 5; ch++) {
        int cur = ch & 1;
        if (ch < 4) { stage(ch + 1, cur ^ 1); CP_COMMIT(); CP_WAIT1(); }
        else        { CP_WAIT0(); }
        __syncthreads();

        uint32_t xb = cur ? xs_base1 : xs_base0;
        uint32_t wb2 = cur ? ws_base1 : ws_base0;
        uint32_t a[2][4];
        #pragma unroll
        for (int ks = 0; ks < 2; ks++)
            ldsm_x4t(a[ks], xb + (uint32_t)((ks*16 + arow)*136 + acol)*2);
        #pragma unroll
        for (int ks = 0; ks < 2; ks++) {
            #pragma unroll
            for (int u = 0; u < 8; u++) {
                uint32_t bf[4];
                ldsm_x4t(bf, wb2 + (uint32_t)((ks*16 + brow)*136 + u*16 + bcol)*2);
                mma_bf16(o[2*u],   a[ks], bf[0], bf[1]);
                mma_bf16(o[2*u+1], a[ks], bf[2], bf[3]);
            }
        }
        __syncthreads();
    }

    int s_row = pt*128 + q0 + g;
    #pragma unroll
    for (int ct = 0; ct < 16; ct++) {
        int c = ct*8 + 2*t;
        float bL = bias[e*128 + c], bH = bias[e*128 + c + 1];
        *(uint32_t*)&dst[(size_t)s_row*C_ + c]       = pack_bf16(o[ct][0] + bL, o[ct][1] + bH);
        *(uint32_t*)&dst[(size_t)(s_row + 8)*C_ + c] = pack_bf16(o[ct][2] + bL, o[ct][3] + bH);
    }
}

// ---------------------------------------------------------------------------
// Attention: bf16 mma + ldmatrix + cp.async, 4 warps x 32 query rows.
// Each K/V fragment feeds 4 mmas (2 m-tiles) -> halved smem amplification.
// smem: K0 @0, K1 @17408, V0 @34816, V1 @52224. Q/epilogue alias. 69632 B.
// ---------------------------------------------------------------------------
#define PAD16 136
#define KVBUF 17408
#define ATTN_SMEM 69632

__global__ void __launch_bounds__(128, 2) attn_bf16_kernel(
    const __nv_bfloat16* __restrict__ gq, const __nv_bfloat16* __restrict__ gk,
    const __nv_bfloat16* __restrict__ gv, __nv_bfloat16* __restrict__ hh)
{
    extern __shared__ char smraw[];
    __nv_bfloat16* qsm = (__nv_bfloat16*)smraw;   // [128][136] staging
    float*         osm = (float*)smraw;           // [128][132] epilogue
    const uint32_t smbase = smem_u32(smraw);

    const int tid  = threadIdx.x;
    const int warp = tid >> 5;
    const int lane = tid & 31;
    const int g    = lane >> 2;
    const int t    = lane & 3;
    const int q0   = warp * 32;

    int qt = blockIdx.x;
    int z  = blockIdx.y;
    int e  = z & 3, s5 = (z >> 2) % 6, b4 = z / 24;
    const int qtab[6] = {0,1,2,3,0,2};
    const int ktab[6] = {1,0,3,2,2,0};

    const __nv_bfloat16* qsrc = gq + (size_t)((b4*4 + qtab[s5])*NH_ + e)*(HW_*C_)
                                   + (size_t)qt*128*C_;
    const __nv_bfloat16* ksrc = gk + (size_t)((b4*4 + ktab[s5])*NH_ + e)*(HW_*C_);
    const __nv_bfloat16* vsrc = gv + (size_t)((b4*4 + ktab[s5])*NH_ + e)*(HW_*C_);
    int idx0 = s5*512 + e*128;
    __nv_bfloat16* out = hh + ((size_t)(b4*4 + idx0/768)*768 + (idx0 % 768)) * HW_;

    // ---- stage Q, load fragments (2 m-tiles per warp) ----
    #pragma unroll
    for (int it = 0; it < 16; it++) {
        int idx = it*128 + tid;
        int r = idx >> 4, c8 = idx & 15;
        *(uint4*)&qsm[r*PAD16 + c8*8] = *(const uint4*)(qsrc + (size_t)r*C_ + c8*8);
    }
    __syncthreads();
    uint32_t qa[2][8][4];
    #pragma unroll
    for (int mt = 0; mt < 2; mt++) {
        int row = q0 + mt*16 + (lane & 7) + ((lane >> 3) & 1)*8;
        int cof = (lane >> 4)*8;
        #pragma unroll
        for (int ks = 0; ks < 8; ks++)
            ldsm_x4(qa[mt][ks], smbase + (uint32_t)(row*PAD16 + ks*16 + cof)*2);
    }
    __syncthreads();

    auto stage_kv = [&](int kt, int st) {
        const __nv_bfloat16* kc = ksrc + (size_t)(kt*64)*C_;
        const __nv_bfloat16* vc = vsrc + (size_t)(kt*64)*C_;
        uint32_t kd = smbase + st*KVBUF;
        uint32_t vd = smbase + (2 + st)*KVBUF;
        #pragma unroll
        for (int it = 0; it < 8; it++) {
            int idx = it*128 + tid;
            int r = idx >> 4, c8 = idx & 15;
            cp_async16(kd + (uint32_t)(r*PAD16 + c8*8)*2, kc + (size_t)r*C_ + c8*8);
            cp_async16(vd + (uint32_t)(r*PAD16 + c8*8)*2, vc + (size_t)r*C_ + c8*8);
        }
    };

    float o[2][16][4];
    #pragma unroll
    for (int mt = 0; mt < 2; mt++)
        #pragma unroll
        for (int ct = 0; ct < 16; ct++)
            #pragma unroll
            for (int j = 0; j < 4; j++) o[mt][ct][j] = 0.f;
    float l[2][2] = {{0.f, 0.f}, {0.f, 0.f}};
    const float K2 = 0.08838834764831845f * 1.4426950408889634f;

    const int krow_lo = (lane & 7);
    const int kcol    = (lane >> 3)*8;
    const int vrow    = (lane & 7) + ((lane >> 3) & 1)*8;
    const int vcol    = (lane >> 4)*8;

    stage_kv(0, 0); CP_COMMIT();

    for (int kt = 0; kt < 16; kt++) {
        int cur = kt & 1;
        if (kt < 15) { stage_kv(kt + 1, cur ^ 1); CP_COMMIT(); CP_WAIT1(); }
        else         { CP_WAIT0(); }
        __syncthreads();

        uint32_t kb2 = smbase + cur*KVBUF;
        uint32_t vb2 = smbase + (2 + cur)*KVBUF;

        #pragma unroll
        for (int j = 0; j < 4; j++) {
            float ca[2][4] = {{0.f,0.f,0.f,0.f},{0.f,0.f,0.f,0.f}};
            float cb[2][4] = {{0.f,0.f,0.f,0.f},{0.f,0.f,0.f,0.f}};
            #pragma unroll
            for (int kbk = 0; kbk < 4; kbk++) {
                uint32_t kfa[4], kfb[4];
                ldsm_x4(kfa, kb2 + (uint32_t)(((2*j)*8 + krow_lo)*PAD16 + kbk*32 + kcol)*2);
                ldsm_x4(kfb, kb2 + (uint32_t)(((2*j+1)*8 + krow_lo)*PAD16 + kbk*32 + kcol)*2);
                #pragma unroll
                for (int mt = 0; mt < 2; mt++) {
                    mma_bf16(ca[mt], qa[mt][2*kbk],   kfa[0], kfa[1]);
                    mma_bf16(ca[mt], qa[mt][2*kbk+1], kfa[2], kfa[3]);
                    mma_bf16(cb[mt], qa[mt][2*kbk],   kfb[0], kfb[1]);
                    mma_bf16(cb[mt], qa[mt][2*kbk+1], kfb[2], kfb[3]);
                }
            }
            uint32_t pA[2][4];
            #pragma unroll
            for (int mt = 0; mt < 2; mt++) {
                float pa0 = fast_ex2(ca[mt][0]*K2), pa1 = fast_ex2(ca[mt][1]*K2);
                float pa2 = fast_ex2(ca[mt][2]*K2), pa3 = fast_ex2(ca[mt][3]*K2);
                float pb0 = fast_ex2(cb[mt][0]*K2), pb1 = fast_ex2(cb[mt][1]*K2);
                float pb2 = fast_ex2(cb[mt][2]*K2), pb3 = fast_ex2(cb[mt][3]*K2);
                l[mt][0] += (pa0 + pa1) + (pb0 + pb1);
                l[mt][1] += (pa2 + pa3) + (pb2 + pb3);
                pA[mt][0] = pack_bf16(pa0, pa1);
                pA[mt][1] = pack_bf16(pa2, pa3);
                pA[mt][2] = pack_bf16(pb0, pb1);
                pA[mt][3] = pack_bf16(pb2, pb3);
            }

            uint32_t vbase = vb2 + (uint32_t)((j*16 + vrow)*PAD16 + vcol)*2;
            #pragma unroll
            for (int u = 0; u < 8; u++) {
                uint32_t vf[4];
                ldsm_x4t(vf, vbase + (uint32_t)(u*16)*2);
                #pragma unroll
                for (int mt = 0; mt < 2; mt++) {
                    mma_bf16(o[mt][2*u],   pA[mt], vf[0], vf[1]);
                    mma_bf16(o[mt][2*u+1], pA[mt], vf[2], vf[3]);
                }
            }
        }
        __syncthreads();
    }

    float inv[2][2];
    #pragma unroll
    for (int mt = 0; mt < 2; mt++) {
        float a0 = l[mt][0], a1 = l[mt][1];
        a0 += __shfl_xor_sync(~0u, a0, 1);
        a0 += __shfl_xor_sync(~0u, a0, 2);
        a1 += __shfl_xor_sync(~0u, a1, 1);
        a1 += __shfl_xor_sync(~0u, a1, 2);
        inv[mt][0] = 1.f / a0;
        inv[mt][1] = 1.f / a1;
    }

    #pragma unroll
    for (int mt = 0; mt < 2; mt++) {
        int r0 = q0 + mt*16;
        #pragma unroll
        for (int ct = 0; ct < 16; ct++) {
            int c = ct*8 + 2*t;
            *(float2*)&osm[(r0 + g)*132 + c] =
                make_float2(o[mt][ct][0]*inv[mt][0], o[mt][ct][1]*inv[mt][0]);
            *(float2*)&osm[(r0 + g + 8)*132 + c] =
                make_float2(o[mt][ct][2]*inv[mt][1], o[mt][ct][3]*inv[mt][1]);
        }
    }
    __syncthreads();
    #pragma unroll
    for (int it = 0; it < 64; it++) {
        int idx = it*128 + tid;
        int c = idx >> 6, qp = idx & 63;
        uint32_t pk = pack_bf16(osm[(2*qp)*132 + c], osm[(2*qp + 1)*132 + c]);
        *(uint32_t*)&out[(size_t)c*HW_ + qt*128 + 2*qp] = pk;
    }
}

// ---------------------------------------------------------------------------
// Output projection: bf16 mma + ldmatrix + cp.async double buffering.
// ---------------------------------------------------------------------------
__global__ void __launch_bounds__(256) out_bf16_kernel(
    const __nv_bfloat16* __restrict__ hh, const float* __restrict__ b3,
    const float* __restrict__ x, float* __restrict__ out)
{
    extern __shared__ __nv_bfloat16 sm2[];
    const uint32_t base = smem_u32(sm2);

    int pt = blockIdx.x;
    int b  = blockIdx.y;
    const __nv_bfloat16* hb = hh + (size_t)b*768*HW_;

    const int tid  = threadIdx.x;
    const int warp = tid >> 5;
    const int lane = tid & 31;
    const int g    = lane >> 2;
    const int t    = lane & 3;
    const int q0   = warp * 16;

    const int arow = (lane & 7) + ((lane >> 4) & 1)*8;
    const int acol = q0 + ((lane >> 3) & 1)*8;
    const int brow = (lane & 7) + ((lane >> 3) & 1)*8;
    const int bcol = (lane >> 4)*8;

    auto stage = [&](int kc, int st) {
        uint32_t ad = base + (uint32_t)(st*8704)*2;
        uint32_t bd = base + (uint32_t)((2 + st)*8704)*2;
        const __nv_bfloat16* asrc = g_w3b + (size_t)(kc*64)*128;
        const __nv_bfloat16* bsrc = hb + (size_t)(kc*64)*HW_ + pt*128;
        #pragma unroll
        for (int it = 0; it < 4; it++) {
            int idx = it*256 + tid;
            int r = idx >> 4, c8 = idx & 15;
            cp_async16(ad + (uint32_t)(r*136 + c8*8)*2, asrc + (size_t)r*128 + c8*8);
            cp_async16(bd + (uint32_t)(r*136 + c8*8)*2, bsrc + (size_t)r*HW_ + c8*8);
        }
    };

    float o[16][4];
    #pragma unroll
    for (int ct = 0; ct < 16; ct++)
        #pragma unroll
        for (int j = 0; j < 4; j++) o[ct][j] = 0.f;

    stage(0, 0); CP_COMMIT();

    for (int kc = 0; kc < 12; kc++) {
        int cur = kc & 1;
        if (kc < 11) { stage(kc + 1, cur ^ 1); CP_COMMIT(); CP_WAIT1(); }
        else         { CP_WAIT0(); }
        __syncthreads();

        uint32_t ab = base + (uint32_t)(cur*8704)*2;
        uint32_t bb = base + (uint32_t)((2 + cur)*8704)*2;

        uint32_t a[4][4];
        #pragma unroll
        for (int ks = 0; ks < 4; ks++)
            ldsm_x4t(a[ks], ab + (uint32_t)((ks*16 + arow)*136 + acol)*2);
        #pragma unroll
        for (int ks = 0; ks < 4; ks++) {
            #pragma unroll
            for (int u = 0; u < 8; u++) {
                uint32_t bf[4];
                ldsm_x4t(bf, bb + (uint32_t)((ks*16 + brow)*136 + u*16 + bcol)*2);
                mma_bf16(o[2*u],   a[ks], bf[0], bf[1]);
                mma_bf16(o[2*u+1], a[ks], bf[2], bf[3]);
            }
        }
        __syncthreads();
    }

    float bb0 = b3[q0 + g];
    float bb1 = b3[q0 + g + 8];
    #pragma unroll
    for (int ct = 0; ct < 16; ct++) {
        size_t a0 = ((size_t)b*C_ + q0 + g)*HW_ + pt*128 + ct*8 + 2*t;
        size_t a1 = ((size_t)b*C_ + q0 + g + 8)*HW_ + pt*128 + ct*8 + 2*t;
        float2 x0 = *(const float2*)&x[a0];
        float2 x1 = *(const float2*)&x[a1];
        *(float2*)&out[a0] = make_float2(o[ct][0] + bb0 + x0.x, o[ct][1] + bb0 + x0.y);
        *(float2*)&out[a1] = make_float2(o[ct][2] + bb1 + x1.x, o[ct][3] + bb1 + x1.y);
    }
}

// ---------------------------------------------------------------------------
extern "C" void kernel_launch(void* const* d_in, const int* in_sizes, int n_in,
                              void* d_out, int out_size)
{
    const float* x      = (const float*)d_in[0];
    const float* q_cond = (const float*)d_in[1];
    const float* ka     = (const float*)d_in[2];
    const float* kb     = (const float*)d_in[3];
    const float* gs     = (const float*)d_in[4];
    const float* gb     = (const float*)d_in[5];
    const float* W0 = (const float*)d_in[6];  const float* b0 = (const float*)d_in[7];
    const float* W1 = (const float*)d_in[8];  const float* b1 = (const float*)d_in[9];
    const float* W2 = (const float*)d_in[10]; const float* b2 = (const float*)d_in[11];
    const float* W3 = (const float*)d_in[12]; const float* b3 = (const float*)d_in[13];
    float* out = (float*)d_out;

    __nv_bfloat16 *h16, *q16, *k16, *v16, *hh16;
    cudaGetSymbolAddress((void**)&h16,  g_h16);
    cudaGetSymbolAddress((void**)&q16,  g_q16);
    cudaGetSymbolAddress((void**)&k16,  g_k16);
    cudaGetSymbolAddress((void**)&v16,  g_v16);
    cudaGetSymbolAddress((void**)&hh16, g_hh16);

    cudaFuncSetAttribute(attn_bf16_kernel,
                         cudaFuncAttributeMaxDynamicSharedMemorySize, ATTN_SMEM);
    const int out_smem = 4 * 8704 * 2;  // 69632 B
    cudaFuncSetAttribute(out_bf16_kernel,
                         cudaFuncAttributeMaxDynamicSharedMemorySize, out_smem);

    dim3 cg(256, 7);
    cvt_kernel<<<cg, 256>>>(W0, W1, W2, W3, q_cond, ka, kb);

    gn_kernel<<<512, 256>>>(x, gs, gb, h16);

    dim3 pg(8, 4, 48);
    proj_bf16_kernel<<<pg, 256>>>(h16, b0, b1, b2, q16, k16, v16);

    dim3 ag(8, 96);
    attn_bf16_kernel<<<ag, 128, ATTN_SMEM>>>(q16, k16, v16, hh16);

    dim3 og(8, 16);
    out_bf16_kernel<<<og, 256, out_smem>>>(hh16, b3, x, out);
}

// round 9
// speedup vs baseline: 1.0137x; 1.0137x over previous
#include <cuda_runtime.h>
#include <cuda_bf16.h>
#include <cstdint>

#define B_   16
#define C_   128
#define HW_  1024
#define NH_  4
#define COND_ 32

// Scratch (device globals; no allocations allowed)
__device__ __nv_bfloat16  g_h16 [B_*C_*HW_];
__device__ __nv_bfloat16  g_q16 [B_*NH_*HW_*C_];
__device__ __nv_bfloat16  g_k16 [B_*NH_*HW_*C_];
__device__ __nv_bfloat16  g_v16 [B_*NH_*HW_*C_];
__device__ __nv_bfloat16  g_hh16[B_*6*C_*HW_];
__device__ __nv_bfloat16  g_w0b[160*512];
__device__ __nv_bfloat16  g_w1b[160*512];
__device__ __nv_bfloat16  g_w2b[160*512];
__device__ __nv_bfloat16  g_w3b[768*128];
__device__ __nv_bfloat16  g_qcb[(B_/2)*COND_*HW_];
__device__ __nv_bfloat16  g_kab[(B_/2)*COND_*HW_];
__device__ __nv_bfloat16  g_kbb[(B_/2)*COND_*HW_];

// ---------------------------------------------------------------------------
__device__ __forceinline__ uint32_t smem_u32(const void* p) {
    uint32_t a;
    asm("{ .reg .u64 t; cvta.to.shared.u64 t, %1; cvt.u32.u64 %0, t; }"
        : "=r"(a) : "l"(p));
    return a;
}
__device__ __forceinline__ uint32_t pack_bf16(float lo, float hi) {
    uint32_t r;
    asm("cvt.rn.bf16x2.f32 %0, %1, %2;" : "=r"(r) : "f"(hi), "f"(lo));
    return r;
}
__device__ __forceinline__ float fast_ex2(float x) {
    float y;
    asm("ex2.approx.f32 %0, %1;" : "=f"(y) : "f"(x));
    return y;
}
__device__ __forceinline__ void mma_bf16(float c[4], const uint32_t a[4],
                                         uint32_t b0, uint32_t b1) {
    asm volatile("mma.sync.aligned.m16n8k16.row.col.f32.bf16.bf16.f32 "
        "{%0,%1,%2,%3}, {%4,%5,%6,%7}, {%8,%9}, {%0,%1,%2,%3};"
        : "+f"(c[0]), "+f"(c[1]), "+f"(c[2]), "+f"(c[3])
        : "r"(a[0]), "r"(a[1]), "r"(a[2]), "r"(a[3]), "r"(b0), "r"(b1));
}
__device__ __forceinline__ void ldsm_x4(uint32_t r[4], uint32_t addr) {
    asm volatile("ldmatrix.sync.aligned.m8n8.x4.shared.b16 {%0,%1,%2,%3}, [%4];"
        : "=r"(r[0]), "=r"(r[1]), "=r"(r[2]), "=r"(r[3]) : "r"(addr));
}
__device__ __forceinline__ void ldsm_x4t(uint32_t r[4], uint32_t addr) {
    asm volatile("ldmatrix.sync.aligned.m8n8.x4.trans.shared.b16 {%0,%1,%2,%3}, [%4];"
        : "=r"(r[0]), "=r"(r[1]), "=r"(r[2]), "=r"(r[3]) : "r"(addr));
}
__device__ __forceinline__ void cp_async16(uint32_t dst, const void* src) {
    asm volatile("cp.async.cg.shared.global [%0], [%1], 16;"
                 :: "r"(dst), "l"(src) : "memory");
}
#define CP_COMMIT() asm volatile("cp.async.commit_group;" ::: "memory")
#define CP_WAIT1()  asm volatile("cp.async.wait_group 1;" ::: "memory")
#define CP_WAIT0()  asm volatile("cp.async.wait_group 0;" ::: "memory")

// ---------------------------------------------------------------------------
// fp32 -> bf16 conversion of weights + cond tensors
// ---------------------------------------------------------------------------
__global__ void __launch_bounds__(256) cvt_kernel(
    const float* __restrict__ W0, const float* __restrict__ W1,
    const float* __restrict__ W2, const float* __restrict__ W3,
    const float* __restrict__ qc, const float* __restrict__ ka,
    const float* __restrict__ kb)
{
    const float* src; __nv_bfloat16* dst; int n;
    switch (blockIdx.y) {
        case 0: src = W0; dst = g_w0b; n = 160*512;          break;
        case 1: src = W1; dst = g_w1b; n = 160*512;          break;
        case 2: src = W2; dst = g_w2b; n = 160*512;          break;
        case 3: src = W3; dst = g_w3b; n = 768*128;          break;
        case 4: src = qc; dst = g_qcb; n = (B_/2)*COND_*HW_; break;
        case 5: src = ka; dst = g_kab; n = (B_/2)*COND_*HW_; break;
        default: src = kb; dst = g_kbb; n = (B_/2)*COND_*HW_; break;
    }
    for (int i = (blockIdx.x*256 + threadIdx.x)*4; i < n; i += 256*256*4) {
        float4 v = *(const float4*)&src[i];
        *(uint2*)&dst[i] = make_uint2(pack_bf16(v.x, v.y), pack_bf16(v.z, v.w));
    }
}

// ---------------------------------------------------------------------------
// GroupNorm -> bf16
// ---------------------------------------------------------------------------
__global__ void __launch_bounds__(256) gn_kernel(
    const float* __restrict__ x, const float* __restrict__ scale,
    const float* __restrict__ bias, __nv_bfloat16* __restrict__ h)
{
    int b = blockIdx.x >> 5, grp = blockIdx.x & 31;
    const float* xp = x + (size_t)(b*C_ + grp*4)*HW_;
    __nv_bfloat16* hp = h + (size_t)(b*C_ + grp*4)*HW_;

    float s = 0.f, ss = 0.f;
    for (int i = threadIdx.x; i < 2048; i += 256) {
        float2 v = *(const float2*)&xp[i*2];
        s += v.x + v.y; ss += v.x*v.x + v.y*v.y;
    }
    #pragma unroll
    for (int o = 16; o; o >>= 1) {
        s  += __shfl_xor_sync(~0u, s,  o);
        ss += __shfl_xor_sync(~0u, ss, o);
    }
    __shared__ float sh_s[8], sh_ss[8];
    int w = threadIdx.x >> 5;
    if ((threadIdx.x & 31) == 0) { sh_s[w] = s; sh_ss[w] = ss; }
    __syncthreads();
    if (threadIdx.x < 32) {
        s  = (threadIdx.x < 8) ? sh_s [threadIdx.x] : 0.f;
        ss = (threadIdx.x < 8) ? sh_ss[threadIdx.x] : 0.f;
        #pragma unroll
        for (int o = 4; o; o >>= 1) {
            s  += __shfl_xor_sync(~0u, s,  o);
            ss += __shfl_xor_sync(~0u, ss, o);
        }
        if (threadIdx.x == 0) { sh_s[0] = s; sh_ss[0] = ss; }
    }
    __syncthreads();
    float mean = sh_s[0] * (1.f/4096.f);
    float var  = sh_ss[0] * (1.f/4096.f) - mean*mean;
    float inv  = rsqrtf(var + 1e-6f);
    for (int i = threadIdx.x*2; i < 4096; i += 512) {
        int c = grp*4 + (i >> 10);
        float sc = scale[c], bi = bias[c];
        float2 v = *(const float2*)&xp[i];
        *(uint32_t*)&hp[i] = pack_bf16((v.x - mean)*inv*sc + bi,
                                       (v.y - mean)*inv*sc + bi);
    }
}

// ---------------------------------------------------------------------------
// QKV projection (unchanged from R7/R8)
// ---------------------------------------------------------------------------
__global__ void __launch_bounds__(256, 2) proj_bf16_kernel(
    const __nv_bfloat16* __restrict__ h,
    const float* __restrict__ b0, const float* __restrict__ b1,
    const float* __restrict__ b2,
    __nv_bfloat16* __restrict__ q16, __nv_bfloat16* __restrict__ k16,
    __nv_bfloat16* __restrict__ v16)
{
    int pt = blockIdx.x;
    int e  = blockIdx.y;
    int b  = blockIdx.z / 3, pr = blockIdx.z % 3;

    const __nv_bfloat16* Wb; const float* bias; const __nv_bfloat16* cond;
    __nv_bfloat16* dstb;
    if (pr == 0) { Wb = g_w0b; bias = b0; dstb = q16; cond = g_qcb + (size_t)(b>>1)*COND_*HW_; }
    else {
        cond = (((b & 1) ? g_kbb : g_kab)) + (size_t)(b>>1)*COND_*HW_;
        if (pr == 1) { Wb = g_w1b; bias = b1; dstb = k16; }
        else         { Wb = g_w2b; bias = b2; dstb = v16; }
    }
    const __nv_bfloat16* hb = h + (size_t)b*C_*HW_;
    __nv_bfloat16* dst = dstb + (size_t)(b*NH_ + e)*HW_*C_;

    __shared__ __nv_bfloat16 Xs[2][32*136];
    __shared__ __nv_bfloat16 Ws[2][32*136];
    const uint32_t xs_base0 = smem_u32(&Xs[0][0]);
    const uint32_t xs_base1 = smem_u32(&Xs[1][0]);
    const uint32_t ws_base0 = smem_u32(&Ws[0][0]);
    const uint32_t ws_base1 = smem_u32(&Ws[1][0]);

    const int tid  = threadIdx.x;
    const int warp = tid >> 5;
    const int lane = tid & 31;
    const int g    = lane >> 2;
    const int t    = lane & 3;
    const int q0   = warp * 16;

    const int arow = (lane & 7) + ((lane >> 4) & 1)*8;
    const int acol = q0 + ((lane >> 3) & 1)*8;
    const int brow = (lane & 7) + ((lane >> 3) & 1)*8;
    const int bcol = (lane >> 4)*8;

    auto stage = [&](int ch, int st) {
        uint32_t xd = st ? xs_base1 : xs_base0;
        uint32_t wd = st ? ws_base1 : ws_base0;
        const __nv_bfloat16* xsrc = (ch < 4) ? (hb + (size_t)(ch*32)*HW_ + pt*128)
                                             : (cond + pt*128);
        const __nv_bfloat16* wsrc = Wb + (size_t)(ch*32)*512 + e*128;
        #pragma unroll
        for (int it = 0; it < 2; it++) {
            int idx = it*256 + tid;
            int r = idx >> 4, c8 = idx & 15;
            cp_async16(xd + (uint32_t)(r*136 + c8*8)*2, xsrc + (size_t)r*HW_ + c8*8);
            cp_async16(wd + (uint32_t)(r*136 + c8*8)*2, wsrc + (size_t)r*512 + c8*8);
        }
    };

    float o[16][4];
    #pragma unroll
    for (int ct = 0; ct < 16; ct++)
        #pragma unroll
        for (int j = 0; j < 4; j++) o[ct][j] = 0.f;

    stage(0, 0); CP_COMMIT();

    for (int ch = 0; ch < 5; ch++) {
        int cur = ch & 1;
        if (ch < 4) { stage(ch + 1, cur ^ 1); CP_COMMIT(); CP_WAIT1(); }
        else        { CP_WAIT0(); }
        __syncthreads();

        uint32_t xb = cur ? xs_base1 : xs_base0;
        uint32_t wb2 = cur ? ws_base1 : ws_base0;
        uint32_t a[2][4];
        #pragma unroll
        for (int ks = 0; ks < 2; ks++)
            ldsm_x4t(a[ks], xb + (uint32_t)((ks*16 + arow)*136 + acol)*2);
        #pragma unroll
        for (int ks = 0; ks < 2; ks++) {
            #pragma unroll
            for (int u = 0; u < 8; u++) {
                uint32_t bf[4];
                ldsm_x4t(bf, wb2 + (uint32_t)((ks*16 + brow)*136 + u*16 + bcol)*2);
                mma_bf16(o[2*u],   a[ks], bf[0], bf[1]);
                mma_bf16(o[2*u+1], a[ks], bf[2], bf[3]);
            }
        }
        __syncthreads();
    }

    int s_row = pt*128 + q0 + g;
    #pragma unroll
    for (int ct = 0; ct < 16; ct++) {
        int c = ct*8 + 2*t;
        float bL = bias[e*128 + c], bH = bias[e*128 + c + 1];
        *(uint32_t*)&dst[(size_t)s_row*C_ + c]       = pack_bf16(o[ct][0] + bL, o[ct][1] + bH);
        *(uint32_t*)&dst[(size_t)(s_row + 8)*C_ + c] = pack_bf16(o[ct][2] + bL, o[ct][3] + bH);
    }
}

// ---------------------------------------------------------------------------
// Attention: 256 query rows per CTA (8 warps x 32 rows) to amortize cp.async.
// smem: Q [256][136] bf16 @0 (persistent), K0/K1/V0/V1 rings @69632.
// Epilogue fp32 [256][132] aliases everything. Total 139264 B.
// ---------------------------------------------------------------------------
#define PAD16 136
#define KVBUF 17408
#define QSM_B 69632
#define ATTN_SMEM 139264

__global__ void __launch_bounds__(256, 1) attn_bf16_kernel(
    const __nv_bfloat16* __restrict__ gq, const __nv_bfloat16* __restrict__ gk,
    const __nv_bfloat16* __restrict__ gv, __nv_bfloat16* __restrict__ hh)
{
    extern __shared__ char smraw[];
    __nv_bfloat16* qsm = (__nv_bfloat16*)smraw;   // [256][136] persistent Q
    float*         osm = (float*)smraw;           // [256][132] epilogue alias
    const uint32_t smbase = smem_u32(smraw);

    const int tid  = threadIdx.x;
    const int warp = tid >> 5;
    const int lane = tid & 31;
    const int g    = lane >> 2;
    const int t    = lane & 3;
    const int q0   = warp * 32;

    int qt = blockIdx.x;                  // 4 tiles of 256 queries
    int z  = blockIdx.y;
    int e  = z & 3, s5 = (z >> 2) % 6, b4 = z / 24;
    const int qtab[6] = {0,1,2,3,0,2};
    const int ktab[6] = {1,0,3,2,2,0};

    const __nv_bfloat16* qsrc = gq + (size_t)((b4*4 + qtab[s5])*NH_ + e)*(HW_*C_)
                                   + (size_t)qt*256*C_;
    const __nv_bfloat16* ksrc = gk + (size_t)((b4*4 + ktab[s5])*NH_ + e)*(HW_*C_);
    const __nv_bfloat16* vsrc = gv + (size_t)((b4*4 + ktab[s5])*NH_ + e)*(HW_*C_);
    int idx0 = s5*512 + e*128;
    __nv_bfloat16* out = hh + ((size_t)(b4*4 + idx0/768)*768 + (idx0 % 768)) * HW_;

    // ---- stage Q [256][136] (cp.async), then fragments to registers ----
    #pragma unroll
    for (int it = 0; it < 16; it++) {
        int idx = it*256 + tid;
        int r = idx >> 4, c8 = idx & 15;
        cp_async16(smbase + (uint32_t)(r*PAD16 + c8*8)*2, qsrc + (size_t)r*C_ + c8*8);
    }
    CP_COMMIT(); CP_WAIT0();
    __syncthreads();

    uint32_t qa[2][8][4];
    #pragma unroll
    for (int mt = 0; mt < 2; mt++) {
        int row = q0 + mt*16 + (lane & 7) + ((lane >> 3) & 1)*8;
        int cof = (lane >> 4)*8;
        #pragma unroll
        for (int ks = 0; ks < 8; ks++)
            ldsm_x4(qa[mt][ks], smbase + (uint32_t)(row*PAD16 + ks*16 + cof)*2);
    }

    auto stage_kv = [&](int kt, int st) {
        const __nv_bfloat16* kc = ksrc + (size_t)(kt*64)*C_;
        const __nv_bfloat16* vc = vsrc + (size_t)(kt*64)*C_;
        uint32_t kd = smbase + QSM_B + st*KVBUF;
        uint32_t vd = smbase + QSM_B + (2 + st)*KVBUF;
        #pragma unroll
        for (int it = 0; it < 4; it++) {
            int idx = it*256 + tid;
            int r = idx >> 4, c8 = idx & 15;
            cp_async16(kd + (uint32_t)(r*PAD16 + c8*8)*2, kc + (size_t)r*C_ + c8*8);
            cp_async16(vd + (uint32_t)(r*PAD16 + c8*8)*2, vc + (size_t)r*C_ + c8*8);
        }
    };

    float o[2][16][4];
    #pragma unroll
    for (int mt = 0; mt < 2; mt++)
        #pragma unroll
        for (int ct = 0; ct < 16; ct++)
            #pragma unroll
            for (int j = 0; j < 4; j++) o[mt][ct][j] = 0.f;
    float l[2][2] = {{0.f, 0.f}, {0.f, 0.f}};
    const float K2 = 0.08838834764831845f * 1.4426950408889634f;

    const int krow_lo = (lane & 7);
    const int kcol    = (lane >> 3)*8;
    const int vrow    = (lane & 7) + ((lane >> 3) & 1)*8;
    const int vcol    = (lane >> 4)*8;

    stage_kv(0, 0); CP_COMMIT();

    for (int kt = 0; kt < 16; kt++) {
        int cur = kt & 1;
        if (kt < 15) { stage_kv(kt + 1, cur ^ 1); CP_COMMIT(); CP_WAIT1(); }
        else         { CP_WAIT0(); }
        __syncthreads();

        uint32_t kb2 = smbase + QSM_B + cur*KVBUF;
        uint32_t vb2 = smbase + QSM_B + (2 + cur)*KVBUF;

        #pragma unroll
        for (int j = 0; j < 4; j++) {
            float ca[2][4] = {{0.f,0.f,0.f,0.f},{0.f,0.f,0.f,0.f}};
            float cb[2][4] = {{0.f,0.f,0.f,0.f},{0.f,0.f,0.f,0.f}};
            #pragma unroll
            for (int kbk = 0; kbk < 4; kbk++) {
                uint32_t kfa[4], kfb[4];
                ldsm_x4(kfa, kb2 + (uint32_t)(((2*j)*8 + krow_lo)*PAD16 + kbk*32 + kcol)*2);
                ldsm_x4(kfb, kb2 + (uint32_t)(((2*j+1)*8 + krow_lo)*PAD16 + kbk*32 + kcol)*2);
                #pragma unroll
                for (int mt = 0; mt < 2; mt++) {
                    mma_bf16(ca[mt], qa[mt][2*kbk],   kfa[0], kfa[1]);
                    mma_bf16(ca[mt], qa[mt][2*kbk+1], kfa[2], kfa[3]);
                    mma_bf16(cb[mt], qa[mt][2*kbk],   kfb[0], kfb[1]);
                    mma_bf16(cb[mt], qa[mt][2*kbk+1], kfb[2], kfb[3]);
                }
            }
            uint32_t pA[2][4];
            #pragma unroll
            for (int mt = 0; mt < 2; mt++) {
                float pa0 = fast_ex2(ca[mt][0]*K2), pa1 = fast_ex2(ca[mt][1]*K2);
                float pa2 = fast_ex2(ca[mt][2]*K2), pa3 = fast_ex2(ca[mt][3]*K2);
                float pb0 = fast_ex2(cb[mt][0]*K2), pb1 = fast_ex2(cb[mt][1]*K2);
                float pb2 = fast_ex2(cb[mt][2]*K2), pb3 = fast_ex2(cb[mt][3]*K2);
                l[mt][0] += (pa0 + pa1) + (pb0 + pb1);
                l[mt][1] += (pa2 + pa3) + (pb2 + pb3);
                pA[mt][0] = pack_bf16(pa0, pa1);
                pA[mt][1] = pack_bf16(pa2, pa3);
                pA[mt][2] = pack_bf16(pb0, pb1);
                pA[mt][3] = pack_bf16(pb2, pb3);
            }

            uint32_t vbase = vb2 + (uint32_t)((j*16 + vrow)*PAD16 + vcol)*2;
            #pragma unroll
            for (int u = 0; u < 8; u++) {
                uint32_t vf[4];
                ldsm_x4t(vf, vbase + (uint32_t)(u*16)*2);
                #pragma unroll
                for (int mt = 0; mt < 2; mt++) {
                    mma_bf16(o[mt][2*u],   pA[mt], vf[0], vf[1]);
                    mma_bf16(o[mt][2*u+1], pA[mt], vf[2], vf[3]);
                }
            }
        }
        __syncthreads();
    }

    float inv[2][2];
    #pragma unroll
    for (int mt = 0; mt < 2; mt++) {
        float a0 = l[mt][0], a1 = l[mt][1];
        a0 += __shfl_xor_sync(~0u, a0, 1);
        a0 += __shfl_xor_sync(~0u, a0, 2);
        a1 += __shfl_xor_sync(~0u, a1, 1);
        a1 += __shfl_xor_sync(~0u, a1, 2);
        inv[mt][0] = 1.f / a0;
        inv[mt][1] = 1.f / a1;
    }

    __syncthreads();   // Q region no longer needed; osm aliases all smem
    #pragma unroll
    for (int mt = 0; mt < 2; mt++) {
        int r0 = q0 + mt*16;
        #pragma unroll
        for (int ct = 0; ct < 16; ct++) {
            int c = ct*8 + 2*t;
            *(float2*)&osm[(r0 + g)*132 + c] =
                make_float2(o[mt][ct][0]*inv[mt][0], o[mt][ct][1]*inv[mt][0]);
            *(float2*)&osm[(r0 + g + 8)*132 + c] =
                make_float2(o[mt][ct][2]*inv[mt][1], o[mt][ct][3]*inv[mt][1]);
        }
    }
    __syncthreads();
    #pragma unroll
    for (int it = 0; it < 64; it++) {
        int idx = it*256 + tid;
        int c = idx >> 7, qp = idx & 127;
        uint32_t pk = pack_bf16(osm[(2*qp)*132 + c], osm[(2*qp + 1)*132 + c]);
        *(uint32_t*)&out[(size_t)c*HW_ + qt*256 + 2*qp] = pk;
    }
}

// ---------------------------------------------------------------------------
// Output projection (unchanged from R7/R8)
// ---------------------------------------------------------------------------
__global__ void __launch_bounds__(256) out_bf16_kernel(
    const __nv_bfloat16* __restrict__ hh, const float* __restrict__ b3,
    const float* __restrict__ x, float* __restrict__ out)
{
    extern __shared__ __nv_bfloat16 sm2[];
    const uint32_t base = smem_u32(sm2);

    int pt = blockIdx.x;
    int b  = blockIdx.y;
    const __nv_bfloat16* hb = hh + (size_t)b*768*HW_;

    const int tid  = threadIdx.x;
    const int warp = tid >> 5;
    const int lane = tid & 31;
    const int g    = lane >> 2;
    const int t    = lane & 3;
    const int q0   = warp * 16;

    const int arow = (lane & 7) + ((lane >> 4) & 1)*8;
    const int acol = q0 + ((lane >> 3) & 1)*8;
    const int brow = (lane & 7) + ((lane >> 3) & 1)*8;
    const int bcol = (lane >> 4)*8;

    auto stage = [&](int kc, int st) {
        uint32_t ad = base + (uint32_t)(st*8704)*2;
        uint32_t bd = base + (uint32_t)((2 + st)*8704)*2;
        const __nv_bfloat16* asrc = g_w3b + (size_t)(kc*64)*128;
        const __nv_bfloat16* bsrc = hb + (size_t)(kc*64)*HW_ + pt*128;
        #pragma unroll
        for (int it = 0; it < 4; it++) {
            int idx = it*256 + tid;
            int r = idx >> 4, c8 = idx & 15;
            cp_async16(ad + (uint32_t)(r*136 + c8*8)*2, asrc + (size_t)r*128 + c8*8);
            cp_async16(bd + (uint32_t)(r*136 + c8*8)*2, bsrc + (size_t)r*HW_ + c8*8);
        }
    };

    float o[16][4];
    #pragma unroll
    for (int ct = 0; ct < 16; ct++)
        #pragma unroll
        for (int j = 0; j < 4; j++) o[ct][j] = 0.f;

    stage(0, 0); CP_COMMIT();

    for (int kc = 0; kc < 12; kc++) {
        int cur = kc & 1;
        if (kc < 11) { stage(kc + 1, cur ^ 1); CP_COMMIT(); CP_WAIT1(); }
        else         { CP_WAIT0(); }
        __syncthreads();

        uint32_t ab = base + (uint32_t)(cur*8704)*2;
        uint32_t bb = base + (uint32_t)((2 + cur)*8704)*2;

        uint32_t a[4][4];
        #pragma unroll
        for (int ks = 0; ks < 4; ks++)
            ldsm_x4t(a[ks], ab + (uint32_t)((ks*16 + arow)*136 + acol)*2);
        #pragma unroll
        for (int ks = 0; ks < 4; ks++) {
            #pragma unroll
            for (int u = 0; u < 8; u++) {
                uint32_t bf[4];
                ldsm_x4t(bf, bb + (uint32_t)((ks*16 + brow)*136 + u*16 + bcol)*2);
                mma_bf16(o[2*u],   a[ks], bf[0], bf[1]);
                mma_bf16(o[2*u+1], a[ks], bf[2], bf[3]);
            }
        }
        __syncthreads();
    }

    float bb0 = b3[q0 + g];
    float bb1 = b3[q0 + g + 8];
    #pragma unroll
    for (int ct = 0; ct < 16; ct++) {
        size_t a0 = ((size_t)b*C_ + q0 + g)*HW_ + pt*128 + ct*8 + 2*t;
        size_t a1 = ((size_t)b*C_ + q0 + g + 8)*HW_ + pt*128 + ct*8 + 2*t;
        float2 x0 = *(const float2*)&x[a0];
        float2 x1 = *(const float2*)&x[a1];
        *(float2*)&out[a0] = make_float2(o[ct][0] + bb0 + x0.x, o[ct][1] + bb0 + x0.y);
        *(float2*)&out[a1] = make_float2(o[ct][2] + bb1 + x1.x, o[ct][3] + bb1 + x1.y);
    }
}

// ---------------------------------------------------------------------------
extern "C" void kernel_launch(void* const* d_in, const int* in_sizes, int n_in,
                              void* d_out, int out_size)
{
    const float* x      = (const float*)d_in[0];
    const float* q_cond = (const float*)d_in[1];
    const float* ka     = (const float*)d_in[2];
    const float* kb     = (const float*)d_in[3];
    const float* gs     = (const float*)d_in[4];
    const float* gb     = (const float*)d_in[5];
    const float* W0 = (const float*)d_in[6];  const float* b0 = (const float*)d_in[7];
    const float* W1 = (const float*)d_in[8];  const float* b1 = (const float*)d_in[9];
    const float* W2 = (const float*)d_in[10]; const float* b2 = (const float*)d_in[11];
    const float* W3 = (const float*)d_in[12]; const float* b3 = (const float*)d_in[13];
    float* out = (float*)d_out;

    __nv_bfloat16 *h16, *q16, *k16, *v16, *hh16;
    cudaGetSymbolAddress((void**)&h16,  g_h16);
    cudaGetSymbolAddress((void**)&q16,  g_q16);
    cudaGetSymbolAddress((void**)&k16,  g_k16);
    cudaGetSymbolAddress((void**)&v16,  g_v16);
    cudaGetSymbolAddress((void**)&hh16, g_hh16);

    cudaFuncSetAttribute(attn_bf16_kernel,
                         cudaFuncAttributeMaxDynamicSharedMemorySize, ATTN_SMEM);
    const int out_smem = 4 * 8704 * 2;  // 69632 B
    cudaFuncSetAttribute(out_bf16_kernel,
                         cudaFuncAttributeMaxDynamicSharedMemorySize, out_smem);

    dim3 cg(256, 7);
    cvt_kernel<<<cg, 256>>>(W0, W1, W2, W3, q_cond, ka, kb);

    gn_kernel<<<512, 256>>>(x, gs, gb, h16);

    dim3 pg(8, 4, 48);
    proj_bf16_kernel<<<pg, 256>>>(h16, b0, b1, b2, q16, k16, v16);

    dim3 ag(4, 96);
    attn_bf16_kernel<<<ag, 256, ATTN_SMEM>>>(q16, k16, v16, hh16);

    dim3 og(8, 16);
    out_bf16_kernel<<<og, 256, out_smem>>>(hh16, b3, x, out);
}

// round 10
// speedup vs baseline: 1.0229x; 1.0091x over previous
#include <cuda_runtime.h>
#include <cuda_bf16.h>
#include <cstdint>

#define B_   16
#define C_   128
#define HW_  1024
#define NH_  4
#define COND_ 32

// Scratch (device globals; no allocations allowed)
__device__ __nv_bfloat16  g_h16 [B_*C_*HW_];
__device__ __nv_bfloat16  g_q16 [B_*NH_*HW_*C_];
__device__ __nv_bfloat16  g_k16 [B_*NH_*HW_*C_];
__device__ __nv_bfloat16  g_v16 [B_*NH_*HW_*C_];
__device__ __nv_bfloat16  g_hh16[B_*6*C_*HW_];
__device__ __nv_bfloat16  g_w0b[160*512];
__device__ __nv_bfloat16  g_w1b[160*512];
__device__ __nv_bfloat16  g_w2b[160*512];
__device__ __nv_bfloat16  g_w3b[768*128];
__device__ __nv_bfloat16  g_qcb[(B_/2)*COND_*HW_];
__device__ __nv_bfloat16  g_kab[(B_/2)*COND_*HW_];
__device__ __nv_bfloat16  g_kbb[(B_/2)*COND_*HW_];

// ---------------------------------------------------------------------------
__device__ __forceinline__ uint32_t smem_u32(const void* p) {
    uint32_t a;
    asm("{ .reg .u64 t; cvta.to.shared.u64 t, %1; cvt.u32.u64 %0, t; }"
        : "=r"(a) : "l"(p));
    return a;
}
__device__ __forceinline__ uint32_t pack_bf16(float lo, float hi) {
    uint32_t r;
    asm("cvt.rn.bf16x2.f32 %0, %1, %2;" : "=r"(r) : "f"(hi), "f"(lo));
    return r;
}
__device__ __forceinline__ float fast_ex2(float x) {
    float y;
    asm("ex2.approx.f32 %0, %1;" : "=f"(y) : "f"(x));
    return y;
}
__device__ __forceinline__ void mma_bf16(float c[4], const uint32_t a[4],
                                         uint32_t b0, uint32_t b1) {
    asm volatile("mma.sync.aligned.m16n8k16.row.col.f32.bf16.bf16.f32 "
        "{%0,%1,%2,%3}, {%4,%5,%6,%7}, {%8,%9}, {%0,%1,%2,%3};"
        : "+f"(c[0]), "+f"(c[1]), "+f"(c[2]), "+f"(c[3])
        : "r"(a[0]), "r"(a[1]), "r"(a[2]), "r"(a[3]), "r"(b0), "r"(b1));
}
__device__ __forceinline__ void ldsm_x4(uint32_t r[4], uint32_t addr) {
    asm volatile("ldmatrix.sync.aligned.m8n8.x4.shared.b16 {%0,%1,%2,%3}, [%4];"
        : "=r"(r[0]), "=r"(r[1]), "=r"(r[2]), "=r"(r[3]) : "r"(addr));
}
__device__ __forceinline__ void ldsm_x4t(uint32_t r[4], uint32_t addr) {
    asm volatile("ldmatrix.sync.aligned.m8n8.x4.trans.shared.b16 {%0,%1,%2,%3}, [%4];"
        : "=r"(r[0]), "=r"(r[1]), "=r"(r[2]), "=r"(r[3]) : "r"(addr));
}
__device__ __forceinline__ void cp_async16(uint32_t dst, const void* src) {
    asm volatile("cp.async.cg.shared.global [%0], [%1], 16;"
                 :: "r"(dst), "l"(src) : "memory");
}
#define CP_COMMIT() asm volatile("cp.async.commit_group;" ::: "memory")
#define CP_WAIT1()  asm volatile("cp.async.wait_group 1;" ::: "memory")
#define CP_WAIT0()  asm volatile("cp.async.wait_group 0;" ::: "memory")

// ---------------------------------------------------------------------------
// Fused GroupNorm (blocks 0..511) + fp32->bf16 weight/cond convert (blocks 512+)
// ---------------------------------------------------------------------------
__global__ void __launch_bounds__(256) gncvt_kernel(
    const float* __restrict__ x, const float* __restrict__ scale,
    const float* __restrict__ bias, __nv_bfloat16* __restrict__ h,
    const float* __restrict__ W0, const float* __restrict__ W1,
    const float* __restrict__ W2, const float* __restrict__ W3,
    const float* __restrict__ qc, const float* __restrict__ ka,
    const float* __restrict__ kb)
{
    int blk = blockIdx.x;
    if (blk >= 512) {
        // ---- convert: each block handles exactly 1024 contiguous elems ----
        int j = blk - 512;
        const float* src; __nv_bfloat16* dst; int base;
        if      (j < 80)   { src = W0; dst = g_w0b; base = j; }
        else if (j < 160)  { src = W1; dst = g_w1b; base = j - 80; }
        else if (j < 240)  { src = W2; dst = g_w2b; base = j - 160; }
        else if (j < 336)  { src = W3; dst = g_w3b; base = j - 240; }
        else if (j < 592)  { src = qc; dst = g_qcb; base = j - 336; }
        else if (j < 848)  { src = ka; dst = g_kab; base = j - 592; }
        else               { src = kb; dst = g_kbb; base = j - 848; }
        int i = base*1024 + threadIdx.x*4;
        float4 v = *(const float4*)&src[i];
        *(uint2*)&dst[i] = make_uint2(pack_bf16(v.x, v.y), pack_bf16(v.z, v.w));
        return;
    }

    // ---- groupnorm: register-cached single pass ----
    int b = blk >> 5, grp = blk & 31;
    const float* xp = x + (size_t)(b*C_ + grp*4)*HW_;
    __nv_bfloat16* hp = h + (size_t)(b*C_ + grp*4)*HW_;

    float v[16];
    float s = 0.f, ss = 0.f;
    #pragma unroll
    for (int it = 0; it < 4; it++) {
        int i = (it*256 + threadIdx.x)*4;
        float4 q = *(const float4*)&xp[i];
        v[it*4+0] = q.x; v[it*4+1] = q.y; v[it*4+2] = q.z; v[it*4+3] = q.w;
        s  += (q.x + q.y) + (q.z + q.w);
        ss += (q.x*q.x + q.y*q.y) + (q.z*q.z + q.w*q.w);
    }
    #pragma unroll
    for (int o = 16; o; o >>= 1) {
        s  += __shfl_xor_sync(~0u, s,  o);
        ss += __shfl_xor_sync(~0u, ss, o);
    }
    __shared__ float sh_s[8], sh_ss[8];
    int w = threadIdx.x >> 5;
    if ((threadIdx.x & 31) == 0) { sh_s[w] = s; sh_ss[w] = ss; }
    __syncthreads();
    if (threadIdx.x < 32) {
        s  = (threadIdx.x < 8) ? sh_s [threadIdx.x] : 0.f;
        ss = (threadIdx.x < 8) ? sh_ss[threadIdx.x] : 0.f;
        #pragma unroll
        for (int o = 4; o; o >>= 1) {
            s  += __shfl_xor_sync(~0u, s,  o);
            ss += __shfl_xor_sync(~0u, ss, o);
        }
        if (threadIdx.x == 0) { sh_s[0] = s; sh_ss[0] = ss; }
    }
    __syncthreads();
    float mean = sh_s[0] * (1.f/4096.f);
    float var  = sh_ss[0] * (1.f/4096.f) - mean*mean;
    float inv  = rsqrtf(var + 1e-6f);
    #pragma unroll
    for (int it = 0; it < 4; it++) {
        int i = (it*256 + threadIdx.x)*4;
        int c = grp*4 + (i >> 10);
        float sc = scale[c]*inv, bi = bias[c] - mean*scale[c]*inv;
        uint2 pk = make_uint2(pack_bf16(v[it*4+0]*sc + bi, v[it*4+1]*sc + bi),
                              pack_bf16(v[it*4+2]*sc + bi, v[it*4+3]*sc + bi));
        *(uint2*)&hp[i] = pk;
    }
}

// ---------------------------------------------------------------------------
// QKV projection (unchanged)
// ---------------------------------------------------------------------------
__global__ void __launch_bounds__(256, 2) proj_bf16_kernel(
    const __nv_bfloat16* __restrict__ h,
    const float* __restrict__ b0, const float* __restrict__ b1,
    const float* __restrict__ b2,
    __nv_bfloat16* __restrict__ q16, __nv_bfloat16* __restrict__ k16,
    __nv_bfloat16* __restrict__ v16)
{
    int pt = blockIdx.x;
    int e  = blockIdx.y;
    int b  = blockIdx.z / 3, pr = blockIdx.z % 3;

    const __nv_bfloat16* Wb; const float* bias; const __nv_bfloat16* cond;
    __nv_bfloat16* dstb;
    if (pr == 0) { Wb = g_w0b; bias = b0; dstb = q16; cond = g_qcb + (size_t)(b>>1)*COND_*HW_; }
    else {
        cond = (((b & 1) ? g_kbb : g_kab)) + (size_t)(b>>1)*COND_*HW_;
        if (pr == 1) { Wb = g_w1b; bias = b1; dstb = k16; }
        else         { Wb = g_w2b; bias = b2; dstb = v16; }
    }
    const __nv_bfloat16* hb = h + (size_t)b*C_*HW_;
    __nv_bfloat16* dst = dstb + (size_t)(b*NH_ + e)*HW_*C_;

    __shared__ __nv_bfloat16 Xs[2][32*136];
    __shared__ __nv_bfloat16 Ws[2][32*136];
    const uint32_t xs_base0 = smem_u32(&Xs[0][0]);
    const uint32_t xs_base1 = smem_u32(&Xs[1][0]);
    const uint32_t ws_base0 = smem_u32(&Ws[0][0]);
    const uint32_t ws_base1 = smem_u32(&Ws[1][0]);

    const int tid  = threadIdx.x;
    const int warp = tid >> 5;
    const int lane = tid & 31;
    const int g    = lane >> 2;
    const int t    = lane & 3;
    const int q0   = warp * 16;

    const int arow = (lane & 7) + ((lane >> 4) & 1)*8;
    const int acol = q0 + ((lane >> 3) & 1)*8;
    const int brow = (lane & 7) + ((lane >> 3) & 1)*8;
    const int bcol = (lane >> 4)*8;

    auto stage = [&](int ch, int st) {
        uint32_t xd = st ? xs_base1 : xs_base0;
        uint32_t wd = st ? ws_base1 : ws_base0;
        const __nv_bfloat16* xsrc = (ch < 4) ? (hb + (size_t)(ch*32)*HW_ + pt*128)
                                             : (cond + pt*128);
        const __nv_bfloat16* wsrc = Wb + (size_t)(ch*32)*512 + e*128;
        #pragma unroll
        for (int it = 0; it < 2; it++) {
            int idx = it*256 + tid;
            int r = idx >> 4, c8 = idx & 15;
            cp_async16(xd + (uint32_t)(r*136 + c8*8)*2, xsrc + (size_t)r*HW_ + c8*8);
            cp_async16(wd + (uint32_t)(r*136 + c8*8)*2, wsrc + (size_t)r*512 + c8*8);
        }
    };

    float o[16][4];
    #pragma unroll
    for (int ct = 0; ct < 16; ct++)
        #pragma unroll
        for (int j = 0; j < 4; j++) o[ct][j] = 0.f;

    stage(0, 0); CP_COMMIT();

    for (int ch = 0; ch < 5; ch++) {
        int cur = ch & 1;
        if (ch < 4) { stage(ch + 1, cur ^ 1); CP_COMMIT(); CP_WAIT1(); }
        else        { CP_WAIT0(); }
        __syncthreads();

        uint32_t xb = cur ? xs_base1 : xs_base0;
        uint32_t wb2 = cur ? ws_base1 : ws_base0;
        uint32_t a[2][4];
        #pragma unroll
        for (int ks = 0; ks < 2; ks++)
            ldsm_x4t(a[ks], xb + (uint32_t)((ks*16 + arow)*136 + acol)*2);
        #pragma unroll
        for (int ks = 0; ks < 2; ks++) {
            #pragma unroll
            for (int u = 0; u < 8; u++) {
                uint32_t bf[4];
                ldsm_x4t(bf, wb2 + (uint32_t)((ks*16 + brow)*136 + u*16 + bcol)*2);
                mma_bf16(o[2*u],   a[ks], bf[0], bf[1]);
                mma_bf16(o[2*u+1], a[ks], bf[2], bf[3]);
            }
        }
        __syncthreads();
    }

    int s_row = pt*128 + q0 + g;
    #pragma unroll
    for (int ct = 0; ct < 16; ct++) {
        int c = ct*8 + 2*t;
        float bL = bias[e*128 + c], bH = bias[e*128 + c + 1];
        *(uint32_t*)&dst[(size_t)s_row*C_ + c]       = pack_bf16(o[ct][0] + bL, o[ct][1] + bH);
        *(uint32_t*)&dst[(size_t)(s_row + 8)*C_ + c] = pack_bf16(o[ct][2] + bL, o[ct][3] + bH);
    }
}

// ---------------------------------------------------------------------------
// Attention (R7 base: 8 warps x 16 rows, 2 CTA/SM) with SPLIT QK accumulator
// chains (depth 8 -> 4) to expose more mma ILP.
// ---------------------------------------------------------------------------
#define PAD16 136
#define KVBUF 17408
#define ATTN_SMEM 69632

__global__ void __launch_bounds__(256, 2) attn_bf16_kernel(
    const __nv_bfloat16* __restrict__ gq, const __nv_bfloat16* __restrict__ gk,
    const __nv_bfloat16* __restrict__ gv, __nv_bfloat16* __restrict__ hh)
{
    extern __shared__ char smraw[];
    __nv_bfloat16* qsm = (__nv_bfloat16*)smraw;
    float*         osm = (float*)smraw;
    const uint32_t smbase = smem_u32(smraw);

    const int tid  = threadIdx.x;
    const int warp = tid >> 5;
    const int lane = tid & 31;
    const int g    = lane >> 2;
    const int t    = lane & 3;
    const int q0   = warp * 16;

    int qt = blockIdx.x;
    int z  = blockIdx.y;
    int e  = z & 3, s5 = (z >> 2) % 6, b4 = z / 24;
    const int qtab[6] = {0,1,2,3,0,2};
    const int ktab[6] = {1,0,3,2,2,0};

    const __nv_bfloat16* qsrc = gq + (size_t)((b4*4 + qtab[s5])*NH_ + e)*(HW_*C_)
                                   + (size_t)qt*128*C_;
    const __nv_bfloat16* ksrc = gk + (size_t)((b4*4 + ktab[s5])*NH_ + e)*(HW_*C_);
    const __nv_bfloat16* vsrc = gv + (size_t)((b4*4 + ktab[s5])*NH_ + e)*(HW_*C_);
    int idx0 = s5*512 + e*128;
    __nv_bfloat16* out = hh + ((size_t)(b4*4 + idx0/768)*768 + (idx0 % 768)) * HW_;

    // ---- stage Q, load fragments ----
    #pragma unroll
    for (int it = 0; it < 8; it++) {
        int idx = it*256 + tid;
        int r = idx >> 4, c8 = idx & 15;
        *(uint4*)&qsm[r*PAD16 + c8*8] = *(const uint4*)(qsrc + (size_t)r*C_ + c8*8);
    }
    __syncthreads();
    uint32_t qa[8][4];
    {
        int row = q0 + (lane & 7) + ((lane >> 3) & 1)*8;
        int cof = (lane >> 4)*8;
        #pragma unroll
        for (int ks = 0; ks < 8; ks++)
            ldsm_x4(qa[ks], smbase + (uint32_t)(row*PAD16 + ks*16 + cof)*2);
    }
    __syncthreads();

    auto stage_kv = [&](int kt, int st) {
        const __nv_bfloat16* kc = ksrc + (size_t)(kt*64)*C_;
        const __nv_bfloat16* vc = vsrc + (size_t)(kt*64)*C_;
        uint32_t kd = smbase + st*KVBUF;
        uint32_t vd = smbase + (2 + st)*KVBUF;
        #pragma unroll
        for (int it = 0; it < 4; it++) {
            int idx = it*256 + tid;
            int r = idx >> 4, c8 = idx & 15;
            cp_async16(kd + (uint32_t)(r*PAD16 + c8*8)*2, kc + (size_t)r*C_ + c8*8);
            cp_async16(vd + (uint32_t)(r*PAD16 + c8*8)*2, vc + (size_t)r*C_ + c8*8);
        }
    };

    float o[16][4];
    #pragma unroll
    for (int ct = 0; ct < 16; ct++)
        #pragma unroll
        for (int j = 0; j < 4; j++) o[ct][j] = 0.f;
    float l0 = 0.f, l1 = 0.f;
    const float K2 = 0.08838834764831845f * 1.4426950408889634f;

    const int krow_lo = (lane & 7);
    const int kcol    = (lane >> 3)*8;
    const int vrow    = (lane & 7) + ((lane >> 3) & 1)*8;
    const int vcol    = (lane >> 4)*8;

    stage_kv(0, 0); CP_COMMIT();

    for (int kt = 0; kt < 16; kt++) {
        int cur = kt & 1;
        if (kt < 15) { stage_kv(kt + 1, cur ^ 1); CP_COMMIT(); CP_WAIT1(); }
        else         { CP_WAIT0(); }
        __syncthreads();

        uint32_t kb2 = smbase + cur*KVBUF;
        uint32_t vb2 = smbase + (2 + cur)*KVBUF;

        #pragma unroll
        for (int j = 0; j < 4; j++) {
            // split accumulator chains: depth 4 instead of 8
            float ca[4] = {0.f,0.f,0.f,0.f}, caX[4] = {0.f,0.f,0.f,0.f};
            float cb[4] = {0.f,0.f,0.f,0.f}, cbX[4] = {0.f,0.f,0.f,0.f};
            #pragma unroll
            for (int kbk = 0; kbk < 4; kbk++) {
                uint32_t kfa[4], kfb[4];
                ldsm_x4(kfa, kb2 + (uint32_t)(((2*j)*8 + krow_lo)*PAD16 + kbk*32 + kcol)*2);
                ldsm_x4(kfb, kb2 + (uint32_t)(((2*j+1)*8 + krow_lo)*PAD16 + kbk*32 + kcol)*2);
                float* cA = (kbk < 2) ? ca : caX;
                float* cB = (kbk < 2) ? cb : cbX;
                mma_bf16((float(&)[4])*cA, qa[2*kbk],   kfa[0], kfa[1]);
                mma_bf16((float(&)[4])*cA, qa[2*kbk+1], kfa[2], kfa[3]);
                mma_bf16((float(&)[4])*cB, qa[2*kbk],   kfb[0], kfb[1]);
                mma_bf16((float(&)[4])*cB, qa[2*kbk+1], kfb[2], kfb[3]);
            }
            #pragma unroll
            for (int i = 0; i < 4; i++) { ca[i] += caX[i]; cb[i] += cbX[i]; }

            float pa0 = fast_ex2(ca[0]*K2), pa1 = fast_ex2(ca[1]*K2);
            float pa2 = fast_ex2(ca[2]*K2), pa3 = fast_ex2(ca[3]*K2);
            float pb0 = fast_ex2(cb[0]*K2), pb1 = fast_ex2(cb[1]*K2);
            float pb2 = fast_ex2(cb[2]*K2), pb3 = fast_ex2(cb[3]*K2);
            l0 += (pa0 + pa1) + (pb0 + pb1);
            l1 += (pa2 + pa3) + (pb2 + pb3);
            uint32_t pA[4];
            pA[0] = pack_bf16(pa0, pa1);
            pA[1] = pack_bf16(pa2, pa3);
            pA[2] = pack_bf16(pb0, pb1);
            pA[3] = pack_bf16(pb2, pb3);

            uint32_t vbase = vb2 + (uint32_t)((j*16 + vrow)*PAD16 + vcol)*2;
            #pragma unroll
            for (int u = 0; u < 8; u++) {
                uint32_t vf[4];
                ldsm_x4t(vf, vbase + (uint32_t)(u*16)*2);
                mma_bf16(o[2*u],   pA, vf[0], vf[1]);
                mma_bf16(o[2*u+1], pA, vf[2], vf[3]);
            }
        }
        __syncthreads();
    }

    l0 += __shfl_xor_sync(~0u, l0, 1);
    l0 += __shfl_xor_sync(~0u, l0, 2);
    l1 += __shfl_xor_sync(~0u, l1, 1);
    l1 += __shfl_xor_sync(~0u, l1, 2);
    float inv0 = 1.f / l0, inv1 = 1.f / l1;

    #pragma unroll
    for (int ct = 0; ct < 16; ct++) {
        int c = ct*8 + 2*t;
        *(float2*)&osm[(q0 + g)*132 + c]     = make_float2(o[ct][0]*inv0, o[ct][1]*inv0);
        *(float2*)&osm[(q0 + g + 8)*132 + c] = make_float2(o[ct][2]*inv1, o[ct][3]*inv1);
    }
    __syncthreads();
    #pragma unroll
    for (int it = 0; it < 32; it++) {
        int idx = it*256 + tid;
        int c = idx >> 6, qp = idx & 63;
        uint32_t pk = pack_bf16(osm[(2*qp)*132 + c], osm[(2*qp + 1)*132 + c]);
        *(uint32_t*)&out[(size_t)c*HW_ + qt*128 + 2*qp] = pk;
    }
}

// ---------------------------------------------------------------------------
// Output projection (unchanged)
// ---------------------------------------------------------------------------
__global__ void __launch_bounds__(256) out_bf16_kernel(
    const __nv_bfloat16* __restrict__ hh, const float* __restrict__ b3,
    const float* __restrict__ x, float* __restrict__ out)
{
    extern __shared__ __nv_bfloat16 sm2[];
    const uint32_t base = smem_u32(sm2);

    int pt = blockIdx.x;
    int b  = blockIdx.y;
    const __nv_bfloat16* hb = hh + (size_t)b*768*HW_;

    const int tid  = threadIdx.x;
    const int warp = tid >> 5;
    const int lane = tid & 31;
    const int g    = lane >> 2;
    const int t    = lane & 3;
    const int q0   = warp * 16;

    const int arow = (lane & 7) + ((lane >> 4) & 1)*8;
    const int acol = q0 + ((lane >> 3) & 1)*8;
    const int brow = (lane & 7) + ((lane >> 3) & 1)*8;
    const int bcol = (lane >> 4)*8;

    auto stage = [&](int kc, int st) {
        uint32_t ad = base + (uint32_t)(st*8704)*2;
        uint32_t bd = base + (uint32_t)((2 + st)*8704)*2;
        const __nv_bfloat16* asrc = g_w3b + (size_t)(kc*64)*128;
        const __nv_bfloat16* bsrc = hb + (size_t)(kc*64)*HW_ + pt*128;
        #pragma unroll
        for (int it = 0; it < 4; it++) {
            int idx = it*256 + tid;
            int r = idx >> 4, c8 = idx & 15;
            cp_async16(ad + (uint32_t)(r*136 + c8*8)*2, asrc + (size_t)r*128 + c8*8);
            cp_async16(bd + (uint32_t)(r*136 + c8*8)*2, bsrc + (size_t)r*HW_ + c8*8);
        }
    };

    float o[16][4];
    #pragma unroll
    for (int ct = 0; ct < 16; ct++)
        #pragma unroll
        for (int j = 0; j < 4; j++) o[ct][j] = 0.f;

    stage(0, 0); CP_COMMIT();

    for (int kc = 0; kc < 12; kc++) {
        int cur = kc & 1;
        if (kc < 11) { stage(kc + 1, cur ^ 1); CP_COMMIT(); CP_WAIT1(); }
        else         { CP_WAIT0(); }
        __syncthreads();

        uint32_t ab = base + (uint32_t)(cur*8704)*2;
        uint32_t bb = base + (uint32_t)((2 + cur)*8704)*2;

        uint32_t a[4][4];
        #pragma unroll
        for (int ks = 0; ks < 4; ks++)
            ldsm_x4t(a[ks], ab + (uint32_t)((ks*16 + arow)*136 + acol)*2);
        #pragma unroll
        for (int ks = 0; ks < 4; ks++) {
            #pragma unroll
            for (int u = 0; u < 8; u++) {
                uint32_t bf[4];
                ldsm_x4t(bf, bb + (uint32_t)((ks*16 + brow)*136 + u*16 + bcol)*2);
                mma_bf16(o[2*u],   a[ks], bf[0], bf[1]);
                mma_bf16(o[2*u+1], a[ks], bf[2], bf[3]);
            }
        }
        __syncthreads();
    }

    float bb0 = b3[q0 + g];
    float bb1 = b3[q0 + g + 8];
    #pragma unroll
    for (int ct = 0; ct < 16; ct++) {
        size_t a0 = ((size_t)b*C_ + q0 + g)*HW_ + pt*128 + ct*8 + 2*t;
        size_t a1 = ((size_t)b*C_ + q0 + g + 8)*HW_ + pt*128 + ct*8 + 2*t;
        float2 x0 = *(const float2*)&x[a0];
        float2 x1 = *(const float2*)&x[a1];
        *(float2*)&out[a0] = make_float2(o[ct][0] + bb0 + x0.x, o[ct][1] + bb0 + x0.y);
        *(float2*)&out[a1] = make_float2(o[ct][2] + bb1 + x1.x, o[ct][3] + bb1 + x1.y);
    }
}

// ---------------------------------------------------------------------------
extern "C" void kernel_launch(void* const* d_in, const int* in_sizes, int n_in,
                              void* d_out, int out_size)
{
    const float* x      = (const float*)d_in[0];
    const float* q_cond = (const float*)d_in[1];
    const float* ka     = (const float*)d_in[2];
    const float* kb     = (const float*)d_in[3];
    const float* gs     = (const float*)d_in[4];
    const float* gb     = (const float*)d_in[5];
    const float* W0 = (const float*)d_in[6];  const float* b0 = (const float*)d_in[7];
    const float* W1 = (const float*)d_in[8];  const float* b1 = (const float*)d_in[9];
    const float* W2 = (const float*)d_in[10]; const float* b2 = (const float*)d_in[11];
    const float* W3 = (const float*)d_in[12]; const float* b3 = (const float*)d_in[13];
    float* out = (float*)d_out;

    __nv_bfloat16 *h16, *q16, *k16, *v16, *hh16;
    cudaGetSymbolAddress((void**)&h16,  g_h16);
    cudaGetSymbolAddress((void**)&q16,  g_q16);
    cudaGetSymbolAddress((void**)&k16,  g_k16);
    cudaGetSymbolAddress((void**)&v16,  g_v16);
    cudaGetSymbolAddress((void**)&hh16, g_hh16);

    cudaFuncSetAttribute(attn_bf16_kernel,
                         cudaFuncAttributeMaxDynamicSharedMemorySize, ATTN_SMEM);
    const int out_smem = 4 * 8704 * 2;
    cudaFuncSetAttribute(out_bf16_kernel,
                         cudaFuncAttributeMaxDynamicSharedMemorySize, out_smem);

    // gn (512 blocks) + cvt (1104 blocks) fused
    gncvt_kernel<<<1616, 256>>>(x, gs, gb, h16, W0, W1, W2, W3, q_cond, ka, kb);

    dim3 pg(8, 4, 48);
    proj_bf16_kernel<<<pg, 256>>>(h16, b0, b1, b2, q16, k16, v16);

    dim3 ag(8, 96);
    attn_bf16_kernel<<<ag, 256, ATTN_SMEM>>>(q16, k16, v16, hh16);

    dim3 og(8, 16);
    out_bf16_kernel<<<og, 256, out_smem>>>(hh16, b3, x, out);
}